// round 1
// baseline (speedup 1.0000x reference)
#include <cuda_runtime.h>

// clip(x + noise, 0, 1) over 50,331,648 fp32 elements.
// HBM-bound: 604 MB traffic -> ~87 us floor at ~7 TB/s.

__global__ void __launch_bounds__(256)
gauss_noise_kernel(const float4* __restrict__ x,
                   const float4* __restrict__ n,
                   float4* __restrict__ out,
                   int nvec) {
    int i = blockIdx.x * blockDim.x + threadIdx.x;
    int stride = gridDim.x * blockDim.x;
    for (; i < nvec; i += stride) {
        float4 a = x[i];
        float4 b = n[i];
        float4 r;
        r.x = __saturatef(a.x + b.x);
        r.y = __saturatef(a.y + b.y);
        r.z = __saturatef(a.z + b.z);
        r.w = __saturatef(a.w + b.w);
        out[i] = r;
    }
}

extern "C" void kernel_launch(void* const* d_in, const int* in_sizes, int n_in,
                              void* d_out, int out_size) {
    const float4* x = (const float4*)d_in[0];
    const float4* n = (const float4*)d_in[1];
    float4* out = (float4*)d_out;

    int nvec = in_sizes[0] / 4;  // 12,582,912
    int threads = 256;
    // Full-chip grid: 148 SMs * 8 CTAs of 256 thr = enough waves with a
    // grid-stride loop; size so each thread does a handful of iterations.
    int blocks = (nvec + threads * 8 - 1) / (threads * 8);
    if (blocks > 65535 * 8) blocks = 65535 * 8;
    gauss_noise_kernel<<<blocks, threads>>>(x, n, out, nvec);
}